// round 12
// baseline (speedup 1.0000x reference)
#include <cuda_runtime.h>
#include <cuda_fp16.h>
#include <cstdint>

#define NN 100000
#define EE 1600000
#define DD 64
#define GG 128
#define BN_EPS 1e-5f
#define SCAN_BS 1024
#define GA_BLOCKS ((NN * 8 + 255) / 256)   // 3125

// ---------------- device scratch (static: no allocation allowed) ----------------
__device__ int       g_deg[NN];
__device__ float     g_dinv[NN];
__device__ int       g_esrc[EE];              // CSR edge sources, grouped by dst
__device__ int       g_rowstart[NN + 1];
__device__ int       g_cursor[NN];
__device__ int       g_bsum[128];
__device__ int       g_dhist[256];            // degree histogram (clamped)
__device__ int       g_dcur[256];             // degree-bucket cursors
__device__ int       g_order[NN];             // nodes sorted by degree
__device__ __half    g_t[(size_t)NN * DD];    // post-GEMM features, fp16, pre-scaled by dinv[row]
__device__ float     g_acc[(size_t)NN * DD];  // aggregated (pre-BN) features, fp32
__device__ float     g_psum[GA_BLOCKS * DD];  // BN partial sums
__device__ float     g_psq[GA_BLOCKS * DD];   // BN partial sum-of-squares
__device__ float     g_scale[DD];
__device__ float     g_shift[DD];
__device__ float     g_gcnt[GG];

__device__ __forceinline__ float to_tf32(float x) {
    uint32_t u;
    asm("cvt.rna.tf32.f32 %0, %1;" : "=r"(u) : "f"(x));
    return __uint_as_float(u);
}

// ---------------- init ----------------
__global__ void init_k(float* out, int N) {
    int i = blockIdx.x * blockDim.x + threadIdx.x;
    if (i < N) g_deg[i] = 0;
    if (i < GG) g_gcnt[i] = 0.f;
    if (i < GG * DD) out[i] = 0.f;
    if (i < 256) g_dhist[i] = 0;
}

// ---------------- degree histogram over dst (4 edges/thread) ----------------
__global__ void deg_k(const int* __restrict__ dst, int E) {
    int e = (blockIdx.x * blockDim.x + threadIdx.x) * 4;
    if (e + 4 <= E) {
        int4 d = *(const int4*)(dst + e);
        atomicAdd(&g_deg[d.x], 1);
        atomicAdd(&g_deg[d.y], 1);
        atomicAdd(&g_deg[d.z], 1);
        atomicAdd(&g_deg[d.w], 1);
    } else {
        for (; e < E; e++) atomicAdd(&g_deg[dst[e]], 1);
    }
}

// ---------------- scan phase 1 (also computes dinv + degree histogram) -------
__global__ void scan1_k(int N) {
    int i = blockIdx.x * SCAN_BS + threadIdx.x;
    int v = (i < N) ? g_deg[i] : 0;
    if (i < N) {
        g_dinv[i] = rsqrtf((float)(v + 1));  // +1 self loop
        atomicAdd(&g_dhist[v < 255 ? v : 255], 1);
    }
    int lane = threadIdx.x & 31, wid = threadIdx.x >> 5;
    int x = v;
    #pragma unroll
    for (int o = 1; o < 32; o <<= 1) {
        int y = __shfl_up_sync(0xffffffffu, x, o);
        if (lane >= o) x += y;
    }
    __shared__ int wsum[32];
    if (lane == 31) wsum[wid] = x;
    __syncthreads();
    if (wid == 0) {
        int y = wsum[lane];
        #pragma unroll
        for (int o = 1; o < 32; o <<= 1) {
            int z = __shfl_up_sync(0xffffffffu, y, o);
            if (lane >= o) y += z;
        }
        wsum[lane] = y;
    }
    __syncthreads();
    int incl = x + (wid > 0 ? wsum[wid - 1] : 0);
    if (i < N) g_rowstart[i] = incl - v;  // block-local exclusive
    if (threadIdx.x == SCAN_BS - 1) g_bsum[blockIdx.x] = incl;
}

// ---------------- exclusive prefix of the 256 degree bins ----------------
__global__ void dprefix_k() {
    int t = threadIdx.x;        // 256
    int lane = t & 31, w = t >> 5;
    int h = g_dhist[t];
    int x = h;
    #pragma unroll
    for (int o = 1; o < 32; o <<= 1) {
        int y = __shfl_up_sync(0xffffffffu, x, o);
        if (lane >= o) x += y;
    }
    __shared__ int ws[8];
    if (lane == 31) ws[w] = x;
    __syncthreads();
    int add = 0;
    #pragma unroll
    for (int j = 0; j < 8; j++) if (j < w) add += ws[j];
    g_dcur[t] = x + add - h;    // exclusive
}

// ---------------- scatter nodes into degree-sorted order ----------------
__global__ void dscatter_k(int N) {
    int i = blockIdx.x * blockDim.x + threadIdx.x;
    if (i < N) {
        int v = g_deg[i];
        int pos = atomicAdd(&g_dcur[v < 255 ? v : 255], 1);
        g_order[pos] = i;
    }
}

// ---------------- scan 2+3 merged: parallel redundant prefix of block sums ----
__global__ void scan3_k(int N, int E, int nb) {
    __shared__ int wsm[4];
    __shared__ int pre[128];
    int t = threadIdx.x;
    int lane = t & 31, w = t >> 5;
    int v = 0, x = 0;
    if (t < 128) {
        v = (t < nb) ? g_bsum[t] : 0;
        x = v;
        #pragma unroll
        for (int o = 1; o < 32; o <<= 1) {
            int y = __shfl_up_sync(0xffffffffu, x, o);
            if (lane >= o) x += y;
        }
        if (lane == 31) wsm[w] = x;
    }
    __syncthreads();
    if (t < 128) {
        int add = 0;
        #pragma unroll
        for (int j = 0; j < 4; j++) if (j < w) add += wsm[j];
        pre[t] = x + add - v;  // exclusive prefix
    }
    __syncthreads();
    int i = blockIdx.x * blockDim.x + t;
    if (i < N) {
        int rs = g_rowstart[i] + pre[i >> 10];
        g_rowstart[i] = rs;
        g_cursor[i] = rs;
    }
    if (i == 0) g_rowstart[N] = E;
}

// ---------------- permute edges into CSR (4 edges/thread) ----------------
__global__ void perm_k(const int* __restrict__ src, const int* __restrict__ dst, int E) {
    int e = (blockIdx.x * blockDim.x + threadIdx.x) * 4;
    if (e + 4 <= E) {
        int4 d = *(const int4*)(dst + e);
        int4 s = *(const int4*)(src + e);
        int p0 = atomicAdd(&g_cursor[d.x], 1);
        int p1 = atomicAdd(&g_cursor[d.y], 1);
        int p2 = atomicAdd(&g_cursor[d.z], 1);
        int p3 = atomicAdd(&g_cursor[d.w], 1);
        g_esrc[p0] = s.x;
        g_esrc[p1] = s.y;
        g_esrc[p2] = s.z;
        g_esrc[p3] = s.w;
    } else {
        for (; e < E; e++) {
            int pos = atomicAdd(&g_cursor[dst[e]], 1);
            g_esrc[pos] = src[e];
        }
    }
}

// ---------------- tensor-core GEMM: g_t[n] = fp16( dinv[n] * (A @ W)[n] )
// A = x (layer 0) or relu(g_acc * scale + shift); tf32 MMA m16n8k8, fp32 accum.
#define AP 68
#define BP 72
__global__ void __launch_bounds__(256, 3)
gemm_mma_k(const float* __restrict__ X, const float* __restrict__ W,
           int layer, int N) {
    __shared__ float As[128 * AP];
    __shared__ float Bs[64 * BP];
    int t = threadIdx.x;
    int row0 = blockIdx.x * 128;
    int lane = t & 31, w = t >> 5;

    #pragma unroll 4
    for (int i = t; i < 64 * 64; i += 256) {
        int k = i >> 6, n = i & 63;
        Bs[k * BP + n] = to_tf32(W[i]);
    }

    {
        int r = t & 127, h = t >> 7;
        int gr = row0 + r;
        bool valid = (gr < N);
        const float* base = (layer == 0) ? X : g_acc;
        const float4* arow = (const float4*)(base + (size_t)gr * 64) + h * 8;
        float* dstrow = As + r * AP + h * 32;
        #pragma unroll
        for (int i = 0; i < 8; i++) {
            float4 v = make_float4(0.f, 0.f, 0.f, 0.f);
            if (valid) {
                v = arow[i];
                if (layer != 0) {
                    float4 sc = ((const float4*)g_scale)[h * 8 + i];
                    float4 sh = ((const float4*)g_shift)[h * 8 + i];
                    v.x = fmaxf(v.x * sc.x + sh.x, 0.f);
                    v.y = fmaxf(v.y * sc.y + sh.y, 0.f);
                    v.z = fmaxf(v.z * sc.z + sh.z, 0.f);
                    v.w = fmaxf(v.w * sc.w + sh.w, 0.f);
                }
            }
            dstrow[i * 4 + 0] = to_tf32(v.x);
            dstrow[i * 4 + 1] = to_tf32(v.y);
            dstrow[i * 4 + 2] = to_tf32(v.z);
            dstrow[i * 4 + 3] = to_tf32(v.w);
        }
    }
    __syncthreads();

    int gq = lane >> 2;
    int qr = lane & 3;
    int arow = w * 16;

    float d[8][4];
    #pragma unroll
    for (int nt = 0; nt < 8; nt++)
        #pragma unroll
        for (int j = 0; j < 4; j++) d[nt][j] = 0.f;

    #pragma unroll
    for (int kk = 0; kk < 8; kk++) {
        int kb = kk * 8;
        uint32_t a0 = __float_as_uint(As[(arow + gq) * AP + kb + qr]);
        uint32_t a1 = __float_as_uint(As[(arow + gq + 8) * AP + kb + qr]);
        uint32_t a2 = __float_as_uint(As[(arow + gq) * AP + kb + qr + 4]);
        uint32_t a3 = __float_as_uint(As[(arow + gq + 8) * AP + kb + qr + 4]);
        #pragma unroll
        for (int nt = 0; nt < 8; nt++) {
            int nb = nt * 8;
            uint32_t b0 = __float_as_uint(Bs[(kb + qr) * BP + nb + gq]);
            uint32_t b1 = __float_as_uint(Bs[(kb + qr + 4) * BP + nb + gq]);
            asm volatile(
                "mma.sync.aligned.m16n8k8.row.col.f32.tf32.tf32.f32 "
                "{%0,%1,%2,%3}, {%4,%5,%6,%7}, {%8,%9}, {%0,%1,%2,%3};"
                : "+f"(d[nt][0]), "+f"(d[nt][1]), "+f"(d[nt][2]), "+f"(d[nt][3])
                : "r"(a0), "r"(a1), "r"(a2), "r"(a3), "r"(b0), "r"(b1));
        }
    }

    #pragma unroll
    for (int hf = 0; hf < 2; hf++) {
        int r = row0 + arow + gq + hf * 8;
        if (r < N) {
            float dv = g_dinv[r];
            #pragma unroll
            for (int nt = 0; nt < 8; nt++) {
                __half2 h = __floats2half2_rn(d[nt][hf * 2 + 0] * dv,
                                              d[nt][hf * 2 + 1] * dv);
                *(__half2*)(g_t + (size_t)r * 64 + nt * 8 + 2 * qr) = h;
            }
        }
    }
}

// ---------------- half2 accumulate helper: 4 HADD2 per edge ----------------
__device__ __forceinline__ void h8_add2(uint4 raw, __half2& a0, __half2& a1,
                                        __half2& a2, __half2& a3) {
    a0 = __hadd2(a0, *(__half2*)&raw.x);
    a1 = __hadd2(a1, *(__half2*)&raw.y);
    a2 = __hadd2(a2, *(__half2*)&raw.z);
    a3 = __hadd2(a3, *(__half2*)&raw.w);
}

// ---------------- CSR gather (degree-sorted node order) + BN partials --------
// 8 lanes per node; nodes taken via g_order so warps/blocks have uniform degree.
__global__ void gather8_k(const float* __restrict__ b, int N) {
    int idx = blockIdx.x * blockDim.x + threadIdx.x;
    int slot_id = idx >> 3;
    int lane = idx & 7;          // owns cols lane*8 .. lane*8+7

    __half2 a0 = __float2half2_rn(0.f), a1 = a0, a2 = a0, a3 = a0;
    float o0 = 0.f, o1 = 0.f, o2 = 0.f, o3 = 0.f,
          o4 = 0.f, o5 = 0.f, o6 = 0.f, o7 = 0.f;
    int node = -1;

    if (slot_id < N) {
        node = g_order[slot_id];

        // self loop
        uint4 raw = *((const uint4*)(g_t + (size_t)node * 64) + lane);
        h8_add2(raw, a0, a1, a2, a3);

        int beg = g_rowstart[node];
        int end = g_rowstart[node + 1];
        int k = beg;
        #pragma unroll 1
        for (; k + 8 <= end; k += 8) {
            uint4 r0 = __ldg((const uint4*)(g_t + (size_t)g_esrc[k + 0] * 64) + lane);
            uint4 r1 = __ldg((const uint4*)(g_t + (size_t)g_esrc[k + 1] * 64) + lane);
            uint4 r2 = __ldg((const uint4*)(g_t + (size_t)g_esrc[k + 2] * 64) + lane);
            uint4 r3 = __ldg((const uint4*)(g_t + (size_t)g_esrc[k + 3] * 64) + lane);
            uint4 r4 = __ldg((const uint4*)(g_t + (size_t)g_esrc[k + 4] * 64) + lane);
            uint4 r5 = __ldg((const uint4*)(g_t + (size_t)g_esrc[k + 5] * 64) + lane);
            uint4 r6 = __ldg((const uint4*)(g_t + (size_t)g_esrc[k + 6] * 64) + lane);
            uint4 r7 = __ldg((const uint4*)(g_t + (size_t)g_esrc[k + 7] * 64) + lane);
            h8_add2(r0, a0, a1, a2, a3); h8_add2(r1, a0, a1, a2, a3);
            h8_add2(r2, a0, a1, a2, a3); h8_add2(r3, a0, a1, a2, a3);
            h8_add2(r4, a0, a1, a2, a3); h8_add2(r5, a0, a1, a2, a3);
            h8_add2(r6, a0, a1, a2, a3); h8_add2(r7, a0, a1, a2, a3);
        }
        if (k + 4 <= end) {
            uint4 r0 = __ldg((const uint4*)(g_t + (size_t)g_esrc[k + 0] * 64) + lane);
            uint4 r1 = __ldg((const uint4*)(g_t + (size_t)g_esrc[k + 1] * 64) + lane);
            uint4 r2 = __ldg((const uint4*)(g_t + (size_t)g_esrc[k + 2] * 64) + lane);
            uint4 r3 = __ldg((const uint4*)(g_t + (size_t)g_esrc[k + 3] * 64) + lane);
            h8_add2(r0, a0, a1, a2, a3); h8_add2(r1, a0, a1, a2, a3);
            h8_add2(r2, a0, a1, a2, a3); h8_add2(r3, a0, a1, a2, a3);
            k += 4;
        }
        if (k + 2 <= end) {
            uint4 r0 = __ldg((const uint4*)(g_t + (size_t)g_esrc[k + 0] * 64) + lane);
            uint4 r1 = __ldg((const uint4*)(g_t + (size_t)g_esrc[k + 1] * 64) + lane);
            h8_add2(r0, a0, a1, a2, a3); h8_add2(r1, a0, a1, a2, a3);
            k += 2;
        }
        if (k < end) {
            uint4 r = __ldg((const uint4*)(g_t + (size_t)g_esrc[k] * 64) + lane);
            h8_add2(r, a0, a1, a2, a3);
        }

        float2 f0 = __half22float2(a0);
        float2 f1 = __half22float2(a1);
        float2 f2 = __half22float2(a2);
        float2 f3 = __half22float2(a3);

        float dv = g_dinv[node];
        float4 bb0 = ((const float4*)b)[lane * 2 + 0];
        float4 bb1 = ((const float4*)b)[lane * 2 + 1];
        o0 = f0.x * dv + bb0.x; o1 = f0.y * dv + bb0.y;
        o2 = f1.x * dv + bb0.z; o3 = f1.y * dv + bb0.w;
        o4 = f2.x * dv + bb1.x; o5 = f2.y * dv + bb1.y;
        o6 = f3.x * dv + bb1.z; o7 = f3.y * dv + bb1.w;

        float* dst = g_acc + (size_t)node * 64 + lane * 8;
        *(float4*)(dst + 0) = make_float4(o0, o1, o2, o3);
        *(float4*)(dst + 4) = make_float4(o4, o5, o6, o7);
    }

    // --- fused BN partial stats: 32 nodes x 64 cols per block ---
    __shared__ float ssum[32][64];
    __shared__ float ssq[32][64];
    int slot = threadIdx.x >> 3;
    int c = lane * 8;
    ssum[slot][c + 0] = o0; ssq[slot][c + 0] = o0 * o0;
    ssum[slot][c + 1] = o1; ssq[slot][c + 1] = o1 * o1;
    ssum[slot][c + 2] = o2; ssq[slot][c + 2] = o2 * o2;
    ssum[slot][c + 3] = o3; ssq[slot][c + 3] = o3 * o3;
    ssum[slot][c + 4] = o4; ssq[slot][c + 4] = o4 * o4;
    ssum[slot][c + 5] = o5; ssq[slot][c + 5] = o5 * o5;
    ssum[slot][c + 6] = o6; ssq[slot][c + 6] = o6 * o6;
    ssum[slot][c + 7] = o7; ssq[slot][c + 7] = o7 * o7;
    __syncthreads();

    if (threadIdx.x < 64) {
        float s = 0.f, q = 0.f;
        #pragma unroll
        for (int r = 0; r < 32; r++) { s += ssum[r][threadIdx.x]; q += ssq[r][threadIdx.x]; }
        g_psum[blockIdx.x * DD + threadIdx.x] = s;
        g_psq[blockIdx.x * DD + threadIdx.x] = q;
    }
}

// ---------------- BN finalize: 64 blocks, one column each ----------------
__global__ void bn_final_k(const float* __restrict__ gamma,
                           const float* __restrict__ beta, int N, int nblocks) {
    int c = blockIdx.x;
    int t = threadIdx.x;     // 256
    float s = 0.f, q = 0.f;
    for (int b = t; b < nblocks; b += 256) {
        s += g_psum[b * DD + c];
        q += g_psq[b * DD + c];
    }
    __shared__ float sh_s[256], sh_q[256];
    sh_s[t] = s; sh_q[t] = q;
    __syncthreads();
    #pragma unroll
    for (int o = 128; o > 0; o >>= 1) {
        if (t < o) { sh_s[t] += sh_s[t + o]; sh_q[t] += sh_q[t + o]; }
        __syncthreads();
    }
    if (t == 0) {
        float inv_n = 1.0f / (float)N;
        float m = sh_s[0] * inv_n;
        float v = sh_q[0] * inv_n - m * m;
        float sc = gamma[c] * rsqrtf(v + BN_EPS);
        g_scale[c] = sc;
        g_shift[c] = beta[c] - m * sc;
    }
}

// ---------------- mean pool (fused BN+ReLU of last layer) ----------------
__global__ void pool_k(const int* __restrict__ batch, float* __restrict__ out, int N) {
    int col = threadIdx.x;  // 64 threads
    int start = blockIdx.x * 128;
    if (start >= N) return;
    int end = min(start + 128, N);
    float sc = g_scale[col];
    float sh = g_shift[col];
    int g = batch[start];
    float s = 0.f;
    float cnt = 0.f;
    for (int n = start; n < end; n++) {
        int gn = batch[n];
        if (gn != g) {
            atomicAdd(&out[g * 64 + col], s);
            if (col == 0) atomicAdd(&g_gcnt[g], cnt);
            s = 0.f; cnt = 0.f; g = gn;
        }
        float a = g_acc[(size_t)n * 64 + col];
        s += fmaxf(a * sc + sh, 0.f);
        cnt += 1.f;
    }
    atomicAdd(&out[g * 64 + col], s);
    if (col == 0) atomicAdd(&g_gcnt[g], cnt);
}

__global__ void scale_out_k(float* out) {
    int i = blockIdx.x * blockDim.x + threadIdx.x;
    if (i < GG * DD) {
        float c = g_gcnt[i >> 6];
        out[i] /= fmaxf(c, 1.f);
    }
}

// ---------------- host launch ----------------
extern "C" void kernel_launch(void* const* d_in, const int* in_sizes, int n_in,
                              void* d_out, int out_size) {
    const float* x      = (const float*)d_in[0];
    const int*   ei     = (const int*)d_in[1];     // int32 (JAX x64 disabled)
    const int*   batch  = (const int*)d_in[2];     // int32
    const float* Ws     = (const float*)d_in[3];
    const float* bs     = (const float*)d_in[4];
    const float* gammas = (const float*)d_in[5];
    const float* betas  = (const float*)d_in[6];
    float*       out    = (float*)d_out;

    int N = in_sizes[0] / DD;   // 100000
    int E = in_sizes[1] / 2;    // 1600000
    const int* src = ei;
    const int* dst = ei + E;

    int tb = 256;
    int nBlk  = (N + tb - 1) / tb;
    int e4Blk = ((E + 3) / 4 + tb - 1) / tb;
    int gaBlk = (N * 8 + tb - 1) / tb;         // 3125
    int gmBlk = (N + 127) / 128;               // 782
    int nScanBlk = (N + SCAN_BS - 1) / SCAN_BS;

    // gemm_mma_k (layer 0) stays the 4th launch — ncu captures launch #4.
    init_k<<<nBlk, tb>>>(out, N);
    deg_k<<<e4Blk, tb>>>(dst, E);
    scan1_k<<<nScanBlk, SCAN_BS>>>(N);
    gemm_mma_k<<<gmBlk, 256>>>(x, Ws + 0 * DD * DD, 0, N);   // 4th launch (profiled)
    dprefix_k<<<1, 256>>>();
    scan3_k<<<nBlk, tb>>>(N, E, nScanBlk);
    dscatter_k<<<nBlk, tb>>>(N);
    perm_k<<<e4Blk, tb>>>(src, dst, E);

    for (int l = 0; l < 3; l++) {
        if (l > 0) gemm_mma_k<<<gmBlk, 256>>>(x, Ws + l * DD * DD, l, N);
        gather8_k<<<gaBlk, tb>>>(bs + l * DD, N);
        bn_final_k<<<64, 256>>>(gammas + l * DD, betas + l * DD, N, gaBlk);
    }

    pool_k<<<(N + 127) / 128, 64>>>(batch, out, N);
    scale_out_k<<<(GG * DD + tb - 1) / tb, tb>>>(out);
}

// round 13
// speedup vs baseline: 1.1404x; 1.1404x over previous
#include <cuda_runtime.h>
#include <cuda_fp16.h>
#include <cstdint>

#define NN 100000
#define EE 1600000
#define DD 64
#define GG 128
#define BN_EPS 1e-5f
#define SCAN_BS 1024
#define GA_BLOCKS ((NN * 8 + 255) / 256)   // 3125

// ---------------- device scratch (static: no allocation allowed) ----------------
__device__ int       g_deg[NN];
__device__ float     g_dinv[NN];
__device__ int       g_esrc[EE];              // CSR edge sources, grouped by dst
__device__ int       g_rowstart[NN + 1];
__device__ int       g_cursor[NN];
__device__ int       g_bsum[128];
__device__ __half    g_t[(size_t)NN * DD];    // post-GEMM features, fp16, pre-scaled by dinv[row]
__device__ float     g_acc[(size_t)NN * DD];  // aggregated (pre-BN) features, fp32
__device__ float     g_psum[GA_BLOCKS * DD];  // BN partial sums
__device__ float     g_psq[GA_BLOCKS * DD];   // BN partial sum-of-squares
__device__ float     g_scale[DD];
__device__ float     g_shift[DD];
__device__ float     g_gcnt[GG];

__device__ __forceinline__ float to_tf32(float x) {
    uint32_t u;
    asm("cvt.rna.tf32.f32 %0, %1;" : "=r"(u) : "f"(x));
    return __uint_as_float(u);
}

// ---------------- init ----------------
__global__ void init_k(float* out, int N) {
    int i = blockIdx.x * blockDim.x + threadIdx.x;
    if (i < N) g_deg[i] = 0;
    if (i < GG) g_gcnt[i] = 0.f;
    if (i < GG * DD) out[i] = 0.f;
}

// ---------------- degree histogram over dst (4 edges/thread) ----------------
__global__ void deg_k(const int* __restrict__ dst, int E) {
    int e = (blockIdx.x * blockDim.x + threadIdx.x) * 4;
    if (e + 4 <= E) {
        int4 d = *(const int4*)(dst + e);
        atomicAdd(&g_deg[d.x], 1);
        atomicAdd(&g_deg[d.y], 1);
        atomicAdd(&g_deg[d.z], 1);
        atomicAdd(&g_deg[d.w], 1);
    } else {
        for (; e < E; e++) atomicAdd(&g_deg[dst[e]], 1);
    }
}

// ---------------- scan phase 1 (also computes dinv) ----------------
__global__ void scan1_k(int N) {
    int i = blockIdx.x * SCAN_BS + threadIdx.x;
    int v = (i < N) ? g_deg[i] : 0;
    if (i < N) g_dinv[i] = rsqrtf((float)(v + 1));  // +1 self loop
    int lane = threadIdx.x & 31, wid = threadIdx.x >> 5;
    int x = v;
    #pragma unroll
    for (int o = 1; o < 32; o <<= 1) {
        int y = __shfl_up_sync(0xffffffffu, x, o);
        if (lane >= o) x += y;
    }
    __shared__ int wsum[32];
    if (lane == 31) wsum[wid] = x;
    __syncthreads();
    if (wid == 0) {
        int y = wsum[lane];
        #pragma unroll
        for (int o = 1; o < 32; o <<= 1) {
            int z = __shfl_up_sync(0xffffffffu, y, o);
            if (lane >= o) y += z;
        }
        wsum[lane] = y;
    }
    __syncthreads();
    int incl = x + (wid > 0 ? wsum[wid - 1] : 0);
    if (i < N) g_rowstart[i] = incl - v;  // block-local exclusive
    if (threadIdx.x == SCAN_BS - 1) g_bsum[blockIdx.x] = incl;
}

// ---------------- scan 2+3 merged: parallel redundant prefix of block sums ----
__global__ void scan3_k(int N, int E, int nb) {
    __shared__ int wsm[4];
    __shared__ int pre[128];
    int t = threadIdx.x;
    int lane = t & 31, w = t >> 5;
    int v = 0, x = 0;
    if (t < 128) {
        v = (t < nb) ? g_bsum[t] : 0;
        x = v;
        #pragma unroll
        for (int o = 1; o < 32; o <<= 1) {
            int y = __shfl_up_sync(0xffffffffu, x, o);
            if (lane >= o) x += y;
        }
        if (lane == 31) wsm[w] = x;
    }
    __syncthreads();
    if (t < 128) {
        int add = 0;
        #pragma unroll
        for (int j = 0; j < 4; j++) if (j < w) add += wsm[j];
        pre[t] = x + add - v;  // exclusive prefix
    }
    __syncthreads();
    int i = blockIdx.x * blockDim.x + t;
    if (i < N) {
        int rs = g_rowstart[i] + pre[i >> 10];
        g_rowstart[i] = rs;
        g_cursor[i] = rs;
    }
    if (i == 0) g_rowstart[N] = E;
}

// ---------------- permute edges into CSR (4 edges/thread) ----------------
__global__ void perm_k(const int* __restrict__ src, const int* __restrict__ dst, int E) {
    int e = (blockIdx.x * blockDim.x + threadIdx.x) * 4;
    if (e + 4 <= E) {
        int4 d = *(const int4*)(dst + e);
        int4 s = *(const int4*)(src + e);
        int p0 = atomicAdd(&g_cursor[d.x], 1);
        int p1 = atomicAdd(&g_cursor[d.y], 1);
        int p2 = atomicAdd(&g_cursor[d.z], 1);
        int p3 = atomicAdd(&g_cursor[d.w], 1);
        g_esrc[p0] = s.x;
        g_esrc[p1] = s.y;
        g_esrc[p2] = s.z;
        g_esrc[p3] = s.w;
    } else {
        for (; e < E; e++) {
            int pos = atomicAdd(&g_cursor[dst[e]], 1);
            g_esrc[pos] = src[e];
        }
    }
}

// ---------------- tensor-core GEMM: g_t[n] = fp16( dinv[n] * (A @ W)[n] )
// A = x (layer 0) or relu(g_acc * scale + shift); tf32 MMA m16n8k8, fp32 accum.
// launch_bounds(256,4): cap at 64 regs -> 4 blocks/SM for latency hiding.
#define AP 68
#define BP 72
__global__ void __launch_bounds__(256, 4)
gemm_mma_k(const float* __restrict__ X, const float* __restrict__ W,
           int layer, int N) {
    __shared__ float As[128 * AP];
    __shared__ float Bs[64 * BP];
    int t = threadIdx.x;
    int row0 = blockIdx.x * 128;
    int lane = t & 31, w = t >> 5;

    #pragma unroll 4
    for (int i = t; i < 64 * 64; i += 256) {
        int k = i >> 6, n = i & 63;
        Bs[k * BP + n] = to_tf32(W[i]);
    }

    {
        int r = t & 127, h = t >> 7;
        int gr = row0 + r;
        bool valid = (gr < N);
        const float* base = (layer == 0) ? X : g_acc;
        const float4* arow = (const float4*)(base + (size_t)gr * 64) + h * 8;
        float* dstrow = As + r * AP + h * 32;
        #pragma unroll
        for (int i = 0; i < 8; i++) {
            float4 v = make_float4(0.f, 0.f, 0.f, 0.f);
            if (valid) {
                v = arow[i];
                if (layer != 0) {
                    float4 sc = ((const float4*)g_scale)[h * 8 + i];
                    float4 sh = ((const float4*)g_shift)[h * 8 + i];
                    v.x = fmaxf(v.x * sc.x + sh.x, 0.f);
                    v.y = fmaxf(v.y * sc.y + sh.y, 0.f);
                    v.z = fmaxf(v.z * sc.z + sh.z, 0.f);
                    v.w = fmaxf(v.w * sc.w + sh.w, 0.f);
                }
            }
            dstrow[i * 4 + 0] = to_tf32(v.x);
            dstrow[i * 4 + 1] = to_tf32(v.y);
            dstrow[i * 4 + 2] = to_tf32(v.z);
            dstrow[i * 4 + 3] = to_tf32(v.w);
        }
    }
    __syncthreads();

    int gq = lane >> 2;
    int qr = lane & 3;
    int arow = w * 16;

    float d[8][4];
    #pragma unroll
    for (int nt = 0; nt < 8; nt++)
        #pragma unroll
        for (int j = 0; j < 4; j++) d[nt][j] = 0.f;

    #pragma unroll
    for (int kk = 0; kk < 8; kk++) {
        int kb = kk * 8;
        uint32_t a0 = __float_as_uint(As[(arow + gq) * AP + kb + qr]);
        uint32_t a1 = __float_as_uint(As[(arow + gq + 8) * AP + kb + qr]);
        uint32_t a2 = __float_as_uint(As[(arow + gq) * AP + kb + qr + 4]);
        uint32_t a3 = __float_as_uint(As[(arow + gq + 8) * AP + kb + qr + 4]);
        #pragma unroll
        for (int nt = 0; nt < 8; nt++) {
            int nb = nt * 8;
            uint32_t b0 = __float_as_uint(Bs[(kb + qr) * BP + nb + gq]);
            uint32_t b1 = __float_as_uint(Bs[(kb + qr + 4) * BP + nb + gq]);
            asm volatile(
                "mma.sync.aligned.m16n8k8.row.col.f32.tf32.tf32.f32 "
                "{%0,%1,%2,%3}, {%4,%5,%6,%7}, {%8,%9}, {%0,%1,%2,%3};"
                : "+f"(d[nt][0]), "+f"(d[nt][1]), "+f"(d[nt][2]), "+f"(d[nt][3])
                : "r"(a0), "r"(a1), "r"(a2), "r"(a3), "r"(b0), "r"(b1));
        }
    }

    #pragma unroll
    for (int hf = 0; hf < 2; hf++) {
        int r = row0 + arow + gq + hf * 8;
        if (r < N) {
            float dv = g_dinv[r];
            #pragma unroll
            for (int nt = 0; nt < 8; nt++) {
                __half2 h = __floats2half2_rn(d[nt][hf * 2 + 0] * dv,
                                              d[nt][hf * 2 + 1] * dv);
                *(__half2*)(g_t + (size_t)r * 64 + nt * 8 + 2 * qr) = h;
            }
        }
    }
}

// ---------------- half2 accumulate helper: 4 HADD2 per edge ----------------
__device__ __forceinline__ void h8_add2(uint4 raw, __half2& a0, __half2& a1,
                                        __half2& a2, __half2& a3) {
    a0 = __hadd2(a0, *(__half2*)&raw.x);
    a1 = __hadd2(a1, *(__half2*)&raw.y);
    a2 = __hadd2(a2, *(__half2*)&raw.z);
    a3 = __hadd2(a3, *(__half2*)&raw.w);
}

// ---------------- CSR gather (fp16 rows, HADD2 accumulate) + BN partials -----
// 8 lanes per node; natural node order (coalesced self-reads + acc writes).
__global__ void gather8_k(const float* __restrict__ b, int N) {
    int idx = blockIdx.x * blockDim.x + threadIdx.x;
    int node = idx >> 3;
    int lane = idx & 7;          // owns cols lane*8 .. lane*8+7

    __half2 a0 = __float2half2_rn(0.f), a1 = a0, a2 = a0, a3 = a0;
    float o0 = 0.f, o1 = 0.f, o2 = 0.f, o3 = 0.f,
          o4 = 0.f, o5 = 0.f, o6 = 0.f, o7 = 0.f;

    if (node < N) {
        // self loop
        uint4 raw = *((const uint4*)(g_t + (size_t)node * 64) + lane);
        h8_add2(raw, a0, a1, a2, a3);

        int beg = g_rowstart[node];
        int end = g_rowstart[node + 1];
        int k = beg;
        #pragma unroll 1
        for (; k + 8 <= end; k += 8) {
            uint4 r0 = __ldg((const uint4*)(g_t + (size_t)g_esrc[k + 0] * 64) + lane);
            uint4 r1 = __ldg((const uint4*)(g_t + (size_t)g_esrc[k + 1] * 64) + lane);
            uint4 r2 = __ldg((const uint4*)(g_t + (size_t)g_esrc[k + 2] * 64) + lane);
            uint4 r3 = __ldg((const uint4*)(g_t + (size_t)g_esrc[k + 3] * 64) + lane);
            uint4 r4 = __ldg((const uint4*)(g_t + (size_t)g_esrc[k + 4] * 64) + lane);
            uint4 r5 = __ldg((const uint4*)(g_t + (size_t)g_esrc[k + 5] * 64) + lane);
            uint4 r6 = __ldg((const uint4*)(g_t + (size_t)g_esrc[k + 6] * 64) + lane);
            uint4 r7 = __ldg((const uint4*)(g_t + (size_t)g_esrc[k + 7] * 64) + lane);
            h8_add2(r0, a0, a1, a2, a3); h8_add2(r1, a0, a1, a2, a3);
            h8_add2(r2, a0, a1, a2, a3); h8_add2(r3, a0, a1, a2, a3);
            h8_add2(r4, a0, a1, a2, a3); h8_add2(r5, a0, a1, a2, a3);
            h8_add2(r6, a0, a1, a2, a3); h8_add2(r7, a0, a1, a2, a3);
        }
        if (k + 4 <= end) {
            uint4 r0 = __ldg((const uint4*)(g_t + (size_t)g_esrc[k + 0] * 64) + lane);
            uint4 r1 = __ldg((const uint4*)(g_t + (size_t)g_esrc[k + 1] * 64) + lane);
            uint4 r2 = __ldg((const uint4*)(g_t + (size_t)g_esrc[k + 2] * 64) + lane);
            uint4 r3 = __ldg((const uint4*)(g_t + (size_t)g_esrc[k + 3] * 64) + lane);
            h8_add2(r0, a0, a1, a2, a3); h8_add2(r1, a0, a1, a2, a3);
            h8_add2(r2, a0, a1, a2, a3); h8_add2(r3, a0, a1, a2, a3);
            k += 4;
        }
        if (k + 2 <= end) {
            uint4 r0 = __ldg((const uint4*)(g_t + (size_t)g_esrc[k + 0] * 64) + lane);
            uint4 r1 = __ldg((const uint4*)(g_t + (size_t)g_esrc[k + 1] * 64) + lane);
            h8_add2(r0, a0, a1, a2, a3); h8_add2(r1, a0, a1, a2, a3);
            k += 2;
        }
        if (k < end) {
            uint4 r = __ldg((const uint4*)(g_t + (size_t)g_esrc[k] * 64) + lane);
            h8_add2(r, a0, a1, a2, a3);
        }

        float2 f0 = __half22float2(a0);
        float2 f1 = __half22float2(a1);
        float2 f2 = __half22float2(a2);
        float2 f3 = __half22float2(a3);

        float dv = g_dinv[node];
        float4 bb0 = ((const float4*)b)[lane * 2 + 0];
        float4 bb1 = ((const float4*)b)[lane * 2 + 1];
        o0 = f0.x * dv + bb0.x; o1 = f0.y * dv + bb0.y;
        o2 = f1.x * dv + bb0.z; o3 = f1.y * dv + bb0.w;
        o4 = f2.x * dv + bb1.x; o5 = f2.y * dv + bb1.y;
        o6 = f3.x * dv + bb1.z; o7 = f3.y * dv + bb1.w;

        float* dst = g_acc + (size_t)node * 64 + lane * 8;
        *(float4*)(dst + 0) = make_float4(o0, o1, o2, o3);
        *(float4*)(dst + 4) = make_float4(o4, o5, o6, o7);
    }

    // --- fused BN partial stats: 32 nodes x 64 cols per block ---
    __shared__ float ssum[32][64];
    __shared__ float ssq[32][64];
    int slot = threadIdx.x >> 3;
    int c = lane * 8;
    ssum[slot][c + 0] = o0; ssq[slot][c + 0] = o0 * o0;
    ssum[slot][c + 1] = o1; ssq[slot][c + 1] = o1 * o1;
    ssum[slot][c + 2] = o2; ssq[slot][c + 2] = o2 * o2;
    ssum[slot][c + 3] = o3; ssq[slot][c + 3] = o3 * o3;
    ssum[slot][c + 4] = o4; ssq[slot][c + 4] = o4 * o4;
    ssum[slot][c + 5] = o5; ssq[slot][c + 5] = o5 * o5;
    ssum[slot][c + 6] = o6; ssq[slot][c + 6] = o6 * o6;
    ssum[slot][c + 7] = o7; ssq[slot][c + 7] = o7 * o7;
    __syncthreads();

    if (threadIdx.x < 64) {
        float s = 0.f, q = 0.f;
        #pragma unroll
        for (int r = 0; r < 32; r++) { s += ssum[r][threadIdx.x]; q += ssq[r][threadIdx.x]; }
        g_psum[blockIdx.x * DD + threadIdx.x] = s;
        g_psq[blockIdx.x * DD + threadIdx.x] = q;
    }
}

// ---------------- BN finalize: 64 blocks, one column each ----------------
__global__ void bn_final_k(const float* __restrict__ gamma,
                           const float* __restrict__ beta, int N, int nblocks) {
    int c = blockIdx.x;
    int t = threadIdx.x;     // 256
    float s = 0.f, q = 0.f;
    for (int b = t; b < nblocks; b += 256) {
        s += g_psum[b * DD + c];
        q += g_psq[b * DD + c];
    }
    __shared__ float sh_s[256], sh_q[256];
    sh_s[t] = s; sh_q[t] = q;
    __syncthreads();
    #pragma unroll
    for (int o = 128; o > 0; o >>= 1) {
        if (t < o) { sh_s[t] += sh_s[t + o]; sh_q[t] += sh_q[t + o]; }
        __syncthreads();
    }
    if (t == 0) {
        float inv_n = 1.0f / (float)N;
        float m = sh_s[0] * inv_n;
        float v = sh_q[0] * inv_n - m * m;
        float sc = gamma[c] * rsqrtf(v + BN_EPS);
        g_scale[c] = sc;
        g_shift[c] = beta[c] - m * sc;
    }
}

// ---------------- mean pool (fused BN+ReLU of last layer) ----------------
__global__ void pool_k(const int* __restrict__ batch, float* __restrict__ out, int N) {
    int col = threadIdx.x;  // 64 threads
    int start = blockIdx.x * 128;
    if (start >= N) return;
    int end = min(start + 128, N);
    float sc = g_scale[col];
    float sh = g_shift[col];
    int g = batch[start];
    float s = 0.f;
    float cnt = 0.f;
    for (int n = start; n < end; n++) {
        int gn = batch[n];
        if (gn != g) {
            atomicAdd(&out[g * 64 + col], s);
            if (col == 0) atomicAdd(&g_gcnt[g], cnt);
            s = 0.f; cnt = 0.f; g = gn;
        }
        float a = g_acc[(size_t)n * 64 + col];
        s += fmaxf(a * sc + sh, 0.f);
        cnt += 1.f;
    }
    atomicAdd(&out[g * 64 + col], s);
    if (col == 0) atomicAdd(&g_gcnt[g], cnt);
}

__global__ void scale_out_k(float* out) {
    int i = blockIdx.x * blockDim.x + threadIdx.x;
    if (i < GG * DD) {
        float c = g_gcnt[i >> 6];
        out[i] /= fmaxf(c, 1.f);
    }
}

// ---------------- host launch ----------------
extern "C" void kernel_launch(void* const* d_in, const int* in_sizes, int n_in,
                              void* d_out, int out_size) {
    const float* x      = (const float*)d_in[0];
    const int*   ei     = (const int*)d_in[1];     // int32 (JAX x64 disabled)
    const int*   batch  = (const int*)d_in[2];     // int32
    const float* Ws     = (const float*)d_in[3];
    const float* bs     = (const float*)d_in[4];
    const float* gammas = (const float*)d_in[5];
    const float* betas  = (const float*)d_in[6];
    float*       out    = (float*)d_out;

    int N = in_sizes[0] / DD;   // 100000
    int E = in_sizes[1] / 2;    // 1600000
    const int* src = ei;
    const int* dst = ei + E;

    int tb = 256;
    int nBlk  = (N + tb - 1) / tb;
    int e4Blk = ((E + 3) / 4 + tb - 1) / tb;
    int gaBlk = (N * 8 + tb - 1) / tb;         // 3125
    int gmBlk = (N + 127) / 128;               // 782
    int nScanBlk = (N + SCAN_BS - 1) / SCAN_BS;

    // gemm_mma_k (layer 0) stays the 4th launch — ncu captures launch #4.
    init_k<<<nBlk, tb>>>(out, N);
    deg_k<<<e4Blk, tb>>>(dst, E);
    scan1_k<<<nScanBlk, SCAN_BS>>>(N);
    gemm_mma_k<<<gmBlk, 256>>>(x, Ws + 0 * DD * DD, 0, N);   // 4th launch (profiled)
    scan3_k<<<nBlk, tb>>>(N, E, nScanBlk);
    perm_k<<<e4Blk, tb>>>(src, dst, E);

    for (int l = 0; l < 3; l++) {
        if (l > 0) gemm_mma_k<<<gmBlk, 256>>>(x, Ws + l * DD * DD, l, N);
        gather8_k<<<gaBlk, tb>>>(bs + l * DD, N);
        bn_final_k<<<64, 256>>>(gammas + l * DD, betas + l * DD, N, gaBlk);
    }

    pool_k<<<(N + 127) / 128, 64>>>(batch, out, N);
    scale_out_k<<<(GG * DD + tb - 1) / tb, tb>>>(out);
}

// round 14
// speedup vs baseline: 1.1739x; 1.0293x over previous
#include <cuda_runtime.h>
#include <cuda_fp16.h>
#include <cstdint>

#define NN 100000
#define EE 1600000
#define DD 64
#define GG 128
#define BN_EPS 1e-5f
#define SCAN_BS 1024
#define GA_BLOCKS ((NN * 8 + 255) / 256)   // 3125

// ---------------- device scratch (static: no allocation allowed) ----------------
__device__ int       g_deg[NN];
__device__ float     g_dinv[NN];
__device__ int       g_esrc[EE];              // CSR edge sources, grouped by dst
__device__ int       g_rowstart[NN + 1];
__device__ int       g_cursor[NN];
__device__ int       g_bsum[128];
__device__ __half    g_t[(size_t)NN * DD];    // post-GEMM features, fp16, pre-scaled by dinv[row]
__device__ float     g_acc[(size_t)NN * DD];  // aggregated (pre-BN) features, fp32
__device__ float     g_psum[GA_BLOCKS * DD];  // BN partial sums
__device__ float     g_psq[GA_BLOCKS * DD];   // BN partial sum-of-squares
__device__ float     g_scale[DD];
__device__ float     g_shift[DD];
__device__ float     g_gcnt[GG];

__device__ __forceinline__ float to_tf32(float x) {
    uint32_t u;
    asm("cvt.rna.tf32.f32 %0, %1;" : "=r"(u) : "f"(x));
    return __uint_as_float(u);
}

// ---------------- init ----------------
__global__ void init_k(float* out, int N) {
    int i = blockIdx.x * blockDim.x + threadIdx.x;
    if (i < N) g_deg[i] = 0;
    if (i < GG) g_gcnt[i] = 0.f;
    if (i < GG * DD) out[i] = 0.f;
}

// ---------------- degree histogram over dst (4 edges/thread) ----------------
__global__ void deg_k(const int* __restrict__ dst, int E) {
    int e = (blockIdx.x * blockDim.x + threadIdx.x) * 4;
    if (e + 4 <= E) {
        int4 d = *(const int4*)(dst + e);
        atomicAdd(&g_deg[d.x], 1);
        atomicAdd(&g_deg[d.y], 1);
        atomicAdd(&g_deg[d.z], 1);
        atomicAdd(&g_deg[d.w], 1);
    } else {
        for (; e < E; e++) atomicAdd(&g_deg[dst[e]], 1);
    }
}

// ---------------- scan phase 1 (also computes dinv) ----------------
__global__ void scan1_k(int N) {
    int i = blockIdx.x * SCAN_BS + threadIdx.x;
    int v = (i < N) ? g_deg[i] : 0;
    if (i < N) g_dinv[i] = rsqrtf((float)(v + 1));  // +1 self loop
    int lane = threadIdx.x & 31, wid = threadIdx.x >> 5;
    int x = v;
    #pragma unroll
    for (int o = 1; o < 32; o <<= 1) {
        int y = __shfl_up_sync(0xffffffffu, x, o);
        if (lane >= o) x += y;
    }
    __shared__ int wsum[32];
    if (lane == 31) wsum[wid] = x;
    __syncthreads();
    if (wid == 0) {
        int y = wsum[lane];
        #pragma unroll
        for (int o = 1; o < 32; o <<= 1) {
            int z = __shfl_up_sync(0xffffffffu, y, o);
            if (lane >= o) y += z;
        }
        wsum[lane] = y;
    }
    __syncthreads();
    int incl = x + (wid > 0 ? wsum[wid - 1] : 0);
    if (i < N) g_rowstart[i] = incl - v;  // block-local exclusive
    if (threadIdx.x == SCAN_BS - 1) g_bsum[blockIdx.x] = incl;
}

// ---------------- scan 2+3 merged: parallel redundant prefix of block sums ----
__global__ void scan3_k(int N, int E, int nb) {
    __shared__ int wsm[4];
    __shared__ int pre[128];
    int t = threadIdx.x;
    int lane = t & 31, w = t >> 5;
    int v = 0, x = 0;
    if (t < 128) {
        v = (t < nb) ? g_bsum[t] : 0;
        x = v;
        #pragma unroll
        for (int o = 1; o < 32; o <<= 1) {
            int y = __shfl_up_sync(0xffffffffu, x, o);
            if (lane >= o) x += y;
        }
        if (lane == 31) wsm[w] = x;
    }
    __syncthreads();
    if (t < 128) {
        int add = 0;
        #pragma unroll
        for (int j = 0; j < 4; j++) if (j < w) add += wsm[j];
        pre[t] = x + add - v;  // exclusive prefix
    }
    __syncthreads();
    int i = blockIdx.x * blockDim.x + t;
    if (i < N) {
        int rs = g_rowstart[i] + pre[i >> 10];
        g_rowstart[i] = rs;
        g_cursor[i] = rs;
    }
    if (i == 0) g_rowstart[N] = E;
}

// ---------------- permute edges into CSR (4 edges/thread) ----------------
__global__ void perm_k(const int* __restrict__ src, const int* __restrict__ dst, int E) {
    int e = (blockIdx.x * blockDim.x + threadIdx.x) * 4;
    if (e + 4 <= E) {
        int4 d = *(const int4*)(dst + e);
        int4 s = *(const int4*)(src + e);
        int p0 = atomicAdd(&g_cursor[d.x], 1);
        int p1 = atomicAdd(&g_cursor[d.y], 1);
        int p2 = atomicAdd(&g_cursor[d.z], 1);
        int p3 = atomicAdd(&g_cursor[d.w], 1);
        g_esrc[p0] = s.x;
        g_esrc[p1] = s.y;
        g_esrc[p2] = s.z;
        g_esrc[p3] = s.w;
    } else {
        for (; e < E; e++) {
            int pos = atomicAdd(&g_cursor[dst[e]], 1);
            g_esrc[pos] = src[e];
        }
    }
}

// ---------------- tensor-core GEMM: g_t[n] = fp16( dinv[n] * (A @ W)[n] )
// A = x (layer 0) or relu(g_acc * scale + shift); tf32 MMA m16n8k8, fp32 accum.
#define AP 68
#define BP 72
__global__ void __launch_bounds__(256, 3)
gemm_mma_k(const float* __restrict__ X, const float* __restrict__ W,
           int layer, int N) {
    __shared__ float As[128 * AP];
    __shared__ float Bs[64 * BP];
    int t = threadIdx.x;
    int row0 = blockIdx.x * 128;
    int lane = t & 31, w = t >> 5;

    #pragma unroll 4
    for (int i = t; i < 64 * 64; i += 256) {
        int k = i >> 6, n = i & 63;
        Bs[k * BP + n] = to_tf32(W[i]);
    }

    {
        int r = t & 127, h = t >> 7;
        int gr = row0 + r;
        bool valid = (gr < N);
        const float* base = (layer == 0) ? X : g_acc;
        const float4* arow = (const float4*)(base + (size_t)gr * 64) + h * 8;
        float* dstrow = As + r * AP + h * 32;
        #pragma unroll
        for (int i = 0; i < 8; i++) {
            float4 v = make_float4(0.f, 0.f, 0.f, 0.f);
            if (valid) {
                v = arow[i];
                if (layer != 0) {
                    float4 sc = ((const float4*)g_scale)[h * 8 + i];
                    float4 sh = ((const float4*)g_shift)[h * 8 + i];
                    v.x = fmaxf(v.x * sc.x + sh.x, 0.f);
                    v.y = fmaxf(v.y * sc.y + sh.y, 0.f);
                    v.z = fmaxf(v.z * sc.z + sh.z, 0.f);
                    v.w = fmaxf(v.w * sc.w + sh.w, 0.f);
                }
            }
            dstrow[i * 4 + 0] = to_tf32(v.x);
            dstrow[i * 4 + 1] = to_tf32(v.y);
            dstrow[i * 4 + 2] = to_tf32(v.z);
            dstrow[i * 4 + 3] = to_tf32(v.w);
        }
    }
    __syncthreads();

    int gq = lane >> 2;
    int qr = lane & 3;
    int arow = w * 16;

    float d[8][4];
    #pragma unroll
    for (int nt = 0; nt < 8; nt++)
        #pragma unroll
        for (int j = 0; j < 4; j++) d[nt][j] = 0.f;

    #pragma unroll
    for (int kk = 0; kk < 8; kk++) {
        int kb = kk * 8;
        uint32_t a0 = __float_as_uint(As[(arow + gq) * AP + kb + qr]);
        uint32_t a1 = __float_as_uint(As[(arow + gq + 8) * AP + kb + qr]);
        uint32_t a2 = __float_as_uint(As[(arow + gq) * AP + kb + qr + 4]);
        uint32_t a3 = __float_as_uint(As[(arow + gq + 8) * AP + kb + qr + 4]);
        #pragma unroll
        for (int nt = 0; nt < 8; nt++) {
            int nb = nt * 8;
            uint32_t b0 = __float_as_uint(Bs[(kb + qr) * BP + nb + gq]);
            uint32_t b1 = __float_as_uint(Bs[(kb + qr + 4) * BP + nb + gq]);
            asm volatile(
                "mma.sync.aligned.m16n8k8.row.col.f32.tf32.tf32.f32 "
                "{%0,%1,%2,%3}, {%4,%5,%6,%7}, {%8,%9}, {%0,%1,%2,%3};"
                : "+f"(d[nt][0]), "+f"(d[nt][1]), "+f"(d[nt][2]), "+f"(d[nt][3])
                : "r"(a0), "r"(a1), "r"(a2), "r"(a3), "r"(b0), "r"(b1));
        }
    }

    #pragma unroll
    for (int hf = 0; hf < 2; hf++) {
        int r = row0 + arow + gq + hf * 8;
        if (r < N) {
            float dv = g_dinv[r];
            #pragma unroll
            for (int nt = 0; nt < 8; nt++) {
                __half2 h = __floats2half2_rn(d[nt][hf * 2 + 0] * dv,
                                              d[nt][hf * 2 + 1] * dv);
                *(__half2*)(g_t + (size_t)r * 64 + nt * 8 + 2 * qr) = h;
            }
        }
    }
}

// ---------------- half2 accumulate helper: 4 HADD2 per edge ----------------
__device__ __forceinline__ void h8_add2(uint4 raw, __half2& a0, __half2& a1,
                                        __half2& a2, __half2& a3) {
    a0 = __hadd2(a0, *(__half2*)&raw.x);
    a1 = __hadd2(a1, *(__half2*)&raw.y);
    a2 = __hadd2(a2, *(__half2*)&raw.z);
    a3 = __hadd2(a3, *(__half2*)&raw.w);
}

// ---------------- CSR gather (fp16 rows, HADD2 accumulate) + BN partials -----
// 8 lanes per node; natural node order (coalesced self-reads + acc writes).
__global__ void gather8_k(const float* __restrict__ b, int N) {
    int idx = blockIdx.x * blockDim.x + threadIdx.x;
    int node = idx >> 3;
    int lane = idx & 7;          // owns cols lane*8 .. lane*8+7

    __half2 a0 = __float2half2_rn(0.f), a1 = a0, a2 = a0, a3 = a0;
    float o0 = 0.f, o1 = 0.f, o2 = 0.f, o3 = 0.f,
          o4 = 0.f, o5 = 0.f, o6 = 0.f, o7 = 0.f;

    if (node < N) {
        // self loop
        uint4 raw = *((const uint4*)(g_t + (size_t)node * 64) + lane);
        h8_add2(raw, a0, a1, a2, a3);

        int beg = g_rowstart[node];
        int end = g_rowstart[node + 1];
        int k = beg;
        #pragma unroll 1
        for (; k + 8 <= end; k += 8) {
            uint4 r0 = __ldg((const uint4*)(g_t + (size_t)g_esrc[k + 0] * 64) + lane);
            uint4 r1 = __ldg((const uint4*)(g_t + (size_t)g_esrc[k + 1] * 64) + lane);
            uint4 r2 = __ldg((const uint4*)(g_t + (size_t)g_esrc[k + 2] * 64) + lane);
            uint4 r3 = __ldg((const uint4*)(g_t + (size_t)g_esrc[k + 3] * 64) + lane);
            uint4 r4 = __ldg((const uint4*)(g_t + (size_t)g_esrc[k + 4] * 64) + lane);
            uint4 r5 = __ldg((const uint4*)(g_t + (size_t)g_esrc[k + 5] * 64) + lane);
            uint4 r6 = __ldg((const uint4*)(g_t + (size_t)g_esrc[k + 6] * 64) + lane);
            uint4 r7 = __ldg((const uint4*)(g_t + (size_t)g_esrc[k + 7] * 64) + lane);
            h8_add2(r0, a0, a1, a2, a3); h8_add2(r1, a0, a1, a2, a3);
            h8_add2(r2, a0, a1, a2, a3); h8_add2(r3, a0, a1, a2, a3);
            h8_add2(r4, a0, a1, a2, a3); h8_add2(r5, a0, a1, a2, a3);
            h8_add2(r6, a0, a1, a2, a3); h8_add2(r7, a0, a1, a2, a3);
        }
        if (k + 4 <= end) {
            uint4 r0 = __ldg((const uint4*)(g_t + (size_t)g_esrc[k + 0] * 64) + lane);
            uint4 r1 = __ldg((const uint4*)(g_t + (size_t)g_esrc[k + 1] * 64) + lane);
            uint4 r2 = __ldg((const uint4*)(g_t + (size_t)g_esrc[k + 2] * 64) + lane);
            uint4 r3 = __ldg((const uint4*)(g_t + (size_t)g_esrc[k + 3] * 64) + lane);
            h8_add2(r0, a0, a1, a2, a3); h8_add2(r1, a0, a1, a2, a3);
            h8_add2(r2, a0, a1, a2, a3); h8_add2(r3, a0, a1, a2, a3);
            k += 4;
        }
        if (k + 2 <= end) {
            uint4 r0 = __ldg((const uint4*)(g_t + (size_t)g_esrc[k + 0] * 64) + lane);
            uint4 r1 = __ldg((const uint4*)(g_t + (size_t)g_esrc[k + 1] * 64) + lane);
            h8_add2(r0, a0, a1, a2, a3); h8_add2(r1, a0, a1, a2, a3);
            k += 2;
        }
        if (k < end) {
            uint4 r = __ldg((const uint4*)(g_t + (size_t)g_esrc[k] * 64) + lane);
            h8_add2(r, a0, a1, a2, a3);
        }

        float2 f0 = __half22float2(a0);
        float2 f1 = __half22float2(a1);
        float2 f2 = __half22float2(a2);
        float2 f3 = __half22float2(a3);

        float dv = g_dinv[node];
        float4 bb0 = ((const float4*)b)[lane * 2 + 0];
        float4 bb1 = ((const float4*)b)[lane * 2 + 1];
        o0 = f0.x * dv + bb0.x; o1 = f0.y * dv + bb0.y;
        o2 = f1.x * dv + bb0.z; o3 = f1.y * dv + bb0.w;
        o4 = f2.x * dv + bb1.x; o5 = f2.y * dv + bb1.y;
        o6 = f3.x * dv + bb1.z; o7 = f3.y * dv + bb1.w;

        float* dst = g_acc + (size_t)node * 64 + lane * 8;
        *(float4*)(dst + 0) = make_float4(o0, o1, o2, o3);
        *(float4*)(dst + 4) = make_float4(o4, o5, o6, o7);
    }

    // --- fused BN partial stats: 32 nodes x 64 cols per block ---
    __shared__ float ssum[32][64];
    __shared__ float ssq[32][64];
    int slot = threadIdx.x >> 3;
    int c = lane * 8;
    ssum[slot][c + 0] = o0; ssq[slot][c + 0] = o0 * o0;
    ssum[slot][c + 1] = o1; ssq[slot][c + 1] = o1 * o1;
    ssum[slot][c + 2] = o2; ssq[slot][c + 2] = o2 * o2;
    ssum[slot][c + 3] = o3; ssq[slot][c + 3] = o3 * o3;
    ssum[slot][c + 4] = o4; ssq[slot][c + 4] = o4 * o4;
    ssum[slot][c + 5] = o5; ssq[slot][c + 5] = o5 * o5;
    ssum[slot][c + 6] = o6; ssq[slot][c + 6] = o6 * o6;
    ssum[slot][c + 7] = o7; ssq[slot][c + 7] = o7 * o7;
    __syncthreads();

    if (threadIdx.x < 64) {
        float s = 0.f, q = 0.f;
        #pragma unroll
        for (int r = 0; r < 32; r++) { s += ssum[r][threadIdx.x]; q += ssq[r][threadIdx.x]; }
        g_psum[blockIdx.x * DD + threadIdx.x] = s;
        g_psq[blockIdx.x * DD + threadIdx.x] = q;
    }
}

// ---------------- BN finalize: 64 blocks, one column each ----------------
__global__ void bn_final_k(const float* __restrict__ gamma,
                           const float* __restrict__ beta, int N, int nblocks) {
    int c = blockIdx.x;
    int t = threadIdx.x;     // 256
    float s = 0.f, q = 0.f;
    for (int b = t; b < nblocks; b += 256) {
        s += g_psum[b * DD + c];
        q += g_psq[b * DD + c];
    }
    __shared__ float sh_s[256], sh_q[256];
    sh_s[t] = s; sh_q[t] = q;
    __syncthreads();
    #pragma unroll
    for (int o = 128; o > 0; o >>= 1) {
        if (t < o) { sh_s[t] += sh_s[t + o]; sh_q[t] += sh_q[t + o]; }
        __syncthreads();
    }
    if (t == 0) {
        float inv_n = 1.0f / (float)N;
        float m = sh_s[0] * inv_n;
        float v = sh_q[0] * inv_n - m * m;
        float sc = gamma[c] * rsqrtf(v + BN_EPS);
        g_scale[c] = sc;
        g_shift[c] = beta[c] - m * sc;
    }
}

// ---------------- mean pool (fused BN+ReLU of last layer) ----------------
__global__ void pool_k(const int* __restrict__ batch, float* __restrict__ out, int N) {
    int col = threadIdx.x;  // 64 threads
    int start = blockIdx.x * 128;
    if (start >= N) return;
    int end = min(start + 128, N);
    float sc = g_scale[col];
    float sh = g_shift[col];
    int g = batch[start];
    float s = 0.f;
    float cnt = 0.f;
    for (int n = start; n < end; n++) {
        int gn = batch[n];
        if (gn != g) {
            atomicAdd(&out[g * 64 + col], s);
            if (col == 0) atomicAdd(&g_gcnt[g], cnt);
            s = 0.f; cnt = 0.f; g = gn;
        }
        float a = g_acc[(size_t)n * 64 + col];
        s += fmaxf(a * sc + sh, 0.f);
        cnt += 1.f;
    }
    atomicAdd(&out[g * 64 + col], s);
    if (col == 0) atomicAdd(&g_gcnt[g], cnt);
}

__global__ void scale_out_k(float* out) {
    int i = blockIdx.x * blockDim.x + threadIdx.x;
    if (i < GG * DD) {
        float c = g_gcnt[i >> 6];
        out[i] /= fmaxf(c, 1.f);
    }
}

// ---------------- host launch: two-stream overlap of gemm0 with CSR build ----
extern "C" void kernel_launch(void* const* d_in, const int* in_sizes, int n_in,
                              void* d_out, int out_size) {
    const float* x      = (const float*)d_in[0];
    const int*   ei     = (const int*)d_in[1];     // int32 (JAX x64 disabled)
    const int*   batch  = (const int*)d_in[2];     // int32
    const float* Ws     = (const float*)d_in[3];
    const float* bs     = (const float*)d_in[4];
    const float* gammas = (const float*)d_in[5];
    const float* betas  = (const float*)d_in[6];
    float*       out    = (float*)d_out;

    int N = in_sizes[0] / DD;   // 100000
    int E = in_sizes[1] / 2;    // 1600000
    const int* src = ei;
    const int* dst = ei + E;

    int tb = 256;
    int nBlk  = (N + tb - 1) / tb;
    int e4Blk = ((E + 3) / 4 + tb - 1) / tb;
    int gaBlk = (N * 8 + tb - 1) / tb;         // 3125
    int gmBlk = (N + 127) / 128;               // 782
    int nScanBlk = (N + SCAN_BS - 1) / SCAN_BS;

    // Streams/events created on first call (uncaptured correctness run);
    // reused identically on every call — same work, same graph.
    static cudaStream_t sA = nullptr, sB = nullptr;
    static cudaEvent_t ev0 = nullptr, evA = nullptr, evB = nullptr, evA2 = nullptr;
    if (sA == nullptr) {
        cudaStreamCreateWithFlags(&sA, cudaStreamNonBlocking);
        cudaStreamCreateWithFlags(&sB, cudaStreamNonBlocking);
        cudaEventCreateWithFlags(&ev0, cudaEventDisableTiming);
        cudaEventCreateWithFlags(&evA, cudaEventDisableTiming);
        cudaEventCreateWithFlags(&evB, cudaEventDisableTiming);
        cudaEventCreateWithFlags(&evA2, cudaEventDisableTiming);
    }

    // fork from the (captured) default stream
    init_k<<<nBlk, tb>>>(out, N);                       // launch 1
    cudaEventRecord(ev0, 0);

    cudaStreamWaitEvent(sA, ev0, 0);
    deg_k<<<e4Blk, tb, 0, sA>>>(dst, E);                // launch 2
    scan1_k<<<nScanBlk, SCAN_BS, 0, sA>>>(N);           // launch 3
    cudaEventRecord(evA, sA);

    // gemm0 needs only g_dinv (scan1) — overlaps with scan3+perm on sA
    cudaStreamWaitEvent(sB, evA, 0);
    gemm_mma_k<<<gmBlk, 256, 0, sB>>>(x, Ws, 0, N);     // launch 4 (profiled)
    cudaEventRecord(evB, sB);

    scan3_k<<<nBlk, tb, 0, sA>>>(N, E, nScanBlk);       // launch 5
    perm_k<<<e4Blk, tb, 0, sA>>>(src, dst, E);          // launch 6
    cudaEventRecord(evA2, sA);

    // join back onto the default stream
    cudaStreamWaitEvent(0, evB, 0);
    cudaStreamWaitEvent(0, evA2, 0);

    for (int l = 0; l < 3; l++) {
        if (l > 0) gemm_mma_k<<<gmBlk, 256>>>(x, Ws + l * DD * DD, l, N);
        gather8_k<<<gaBlk, tb>>>(bs + l * DD, N);
        bn_final_k<<<64, 256>>>(gammas + l * DD, betas + l * DD, N, gaBlk);
    }

    pool_k<<<(N + 127) / 128, 64>>>(batch, out, N);
    scale_out_k<<<(GG * DD + tb - 1) / tb, tb>>>(out);
}

// round 15
// speedup vs baseline: 1.2562x; 1.0702x over previous
#include <cuda_runtime.h>
#include <cuda_fp16.h>
#include <cstdint>

#define NN 100000
#define EE 1600000
#define DD 64
#define GG 128
#define BN_EPS 1e-5f
#define SCAN_BS 1024
#define GA_BLOCKS ((NN * 8 + 255) / 256)   // 3125

// ---------------- device scratch (static: no allocation allowed) ----------------
__device__ int       g_deg[NN];
__device__ float     g_dinv[NN];
__device__ int       g_esrc[EE];              // CSR edge sources, grouped by dst
__device__ int       g_rowstart[NN + 1];
__device__ int       g_cursor[NN];
__device__ int       g_bsum[128];
__device__ __half    g_t[(size_t)NN * DD];    // post-GEMM features, fp16, pre-scaled by dinv[row]
__device__ __half    g_acc[(size_t)NN * DD];  // aggregated (pre-BN) features, fp16
__device__ float     g_psum[GA_BLOCKS * DD];  // BN partial sums (fp32, from registers)
__device__ float     g_psq[GA_BLOCKS * DD];   // BN partial sum-of-squares
__device__ float     g_scale[DD];
__device__ float     g_shift[DD];
__device__ float     g_gcnt[GG];

__device__ __forceinline__ float to_tf32(float x) {
    uint32_t u;
    asm("cvt.rna.tf32.f32 %0, %1;" : "=r"(u) : "f"(x));
    return __uint_as_float(u);
}

// ---------------- init ----------------
__global__ void init_k(float* out, int N) {
    int i = blockIdx.x * blockDim.x + threadIdx.x;
    if (i < N) g_deg[i] = 0;
    if (i < GG) g_gcnt[i] = 0.f;
    if (i < GG * DD) out[i] = 0.f;
}

// ---------------- degree histogram over dst (4 edges/thread) ----------------
__global__ void deg_k(const int* __restrict__ dst, int E) {
    int e = (blockIdx.x * blockDim.x + threadIdx.x) * 4;
    if (e + 4 <= E) {
        int4 d = *(const int4*)(dst + e);
        atomicAdd(&g_deg[d.x], 1);
        atomicAdd(&g_deg[d.y], 1);
        atomicAdd(&g_deg[d.z], 1);
        atomicAdd(&g_deg[d.w], 1);
    } else {
        for (; e < E; e++) atomicAdd(&g_deg[dst[e]], 1);
    }
}

// ---------------- scan phase 1 (also computes dinv) ----------------
__global__ void scan1_k(int N) {
    int i = blockIdx.x * SCAN_BS + threadIdx.x;
    int v = (i < N) ? g_deg[i] : 0;
    if (i < N) g_dinv[i] = rsqrtf((float)(v + 1));  // +1 self loop
    int lane = threadIdx.x & 31, wid = threadIdx.x >> 5;
    int x = v;
    #pragma unroll
    for (int o = 1; o < 32; o <<= 1) {
        int y = __shfl_up_sync(0xffffffffu, x, o);
        if (lane >= o) x += y;
    }
    __shared__ int wsum[32];
    if (lane == 31) wsum[wid] = x;
    __syncthreads();
    if (wid == 0) {
        int y = wsum[lane];
        #pragma unroll
        for (int o = 1; o < 32; o <<= 1) {
            int z = __shfl_up_sync(0xffffffffu, y, o);
            if (lane >= o) y += z;
        }
        wsum[lane] = y;
    }
    __syncthreads();
    int incl = x + (wid > 0 ? wsum[wid - 1] : 0);
    if (i < N) g_rowstart[i] = incl - v;  // block-local exclusive
    if (threadIdx.x == SCAN_BS - 1) g_bsum[blockIdx.x] = incl;
}

// ---------------- scan 2+3 merged: parallel redundant prefix of block sums ----
__global__ void scan3_k(int N, int E, int nb) {
    __shared__ int wsm[4];
    __shared__ int pre[128];
    int t = threadIdx.x;
    int lane = t & 31, w = t >> 5;
    int v = 0, x = 0;
    if (t < 128) {
        v = (t < nb) ? g_bsum[t] : 0;
        x = v;
        #pragma unroll
        for (int o = 1; o < 32; o <<= 1) {
            int y = __shfl_up_sync(0xffffffffu, x, o);
            if (lane >= o) x += y;
        }
        if (lane == 31) wsm[w] = x;
    }
    __syncthreads();
    if (t < 128) {
        int add = 0;
        #pragma unroll
        for (int j = 0; j < 4; j++) if (j < w) add += wsm[j];
        pre[t] = x + add - v;  // exclusive prefix
    }
    __syncthreads();
    int i = blockIdx.x * blockDim.x + t;
    if (i < N) {
        int rs = g_rowstart[i] + pre[i >> 10];
        g_rowstart[i] = rs;
        g_cursor[i] = rs;
    }
    if (i == 0) g_rowstart[N] = E;
}

// ---------------- permute edges into CSR (4 edges/thread) ----------------
__global__ void perm_k(const int* __restrict__ src, const int* __restrict__ dst, int E) {
    int e = (blockIdx.x * blockDim.x + threadIdx.x) * 4;
    if (e + 4 <= E) {
        int4 d = *(const int4*)(dst + e);
        int4 s = *(const int4*)(src + e);
        int p0 = atomicAdd(&g_cursor[d.x], 1);
        int p1 = atomicAdd(&g_cursor[d.y], 1);
        int p2 = atomicAdd(&g_cursor[d.z], 1);
        int p3 = atomicAdd(&g_cursor[d.w], 1);
        g_esrc[p0] = s.x;
        g_esrc[p1] = s.y;
        g_esrc[p2] = s.z;
        g_esrc[p3] = s.w;
    } else {
        for (; e < E; e++) {
            int pos = atomicAdd(&g_cursor[dst[e]], 1);
            g_esrc[pos] = src[e];
        }
    }
}

// ---------------- tensor-core GEMM: g_t[n] = fp16( dinv[n] * (A @ W)[n] )
// A = x fp32 (layer 0) or relu(g_acc_fp16 * scale + shift) (layers > 0)
#define AP 68
#define BP 72
__global__ void __launch_bounds__(256, 3)
gemm_mma_k(const float* __restrict__ X, const float* __restrict__ W,
           int layer, int N) {
    __shared__ float As[128 * AP];
    __shared__ float Bs[64 * BP];
    int t = threadIdx.x;
    int row0 = blockIdx.x * 128;
    int lane = t & 31, w = t >> 5;

    #pragma unroll 4
    for (int i = t; i < 64 * 64; i += 256) {
        int k = i >> 6, n = i & 63;
        Bs[k * BP + n] = to_tf32(W[i]);
    }

    {
        int r = t & 127, h = t >> 7;       // h = 0/1: col halves (32 cols each)
        int gr = row0 + r;
        bool valid = (gr < N);
        float* dstrow = As + r * AP + h * 32;
        if (layer == 0) {
            const float4* arow = (const float4*)(X + (size_t)gr * 64) + h * 8;
            #pragma unroll
            for (int i = 0; i < 8; i++) {
                float4 v = valid ? arow[i] : make_float4(0.f, 0.f, 0.f, 0.f);
                dstrow[i * 4 + 0] = to_tf32(v.x);
                dstrow[i * 4 + 1] = to_tf32(v.y);
                dstrow[i * 4 + 2] = to_tf32(v.z);
                dstrow[i * 4 + 3] = to_tf32(v.w);
            }
        } else {
            // fp16 g_acc: 32 cols = 4 uint4 (8 halfs each)
            const uint4* arow = (const uint4*)(g_acc + (size_t)gr * 64) + h * 4;
            #pragma unroll
            for (int i = 0; i < 4; i++) {
                uint4 raw = valid ? __ldg(arow + i)
                                  : make_uint4(0u, 0u, 0u, 0u);
                float2 p0 = __half22float2(*(__half2*)&raw.x);
                float2 p1 = __half22float2(*(__half2*)&raw.y);
                float2 p2 = __half22float2(*(__half2*)&raw.z);
                float2 p3 = __half22float2(*(__half2*)&raw.w);
                int cb = h * 32 + i * 8;
                float4 sc0 = ((const float4*)g_scale)[cb / 4 + 0];
                float4 sc1 = ((const float4*)g_scale)[cb / 4 + 1];
                float4 sh0 = ((const float4*)g_shift)[cb / 4 + 0];
                float4 sh1 = ((const float4*)g_shift)[cb / 4 + 1];
                dstrow[i * 8 + 0] = to_tf32(fmaxf(p0.x * sc0.x + sh0.x, 0.f));
                dstrow[i * 8 + 1] = to_tf32(fmaxf(p0.y * sc0.y + sh0.y, 0.f));
                dstrow[i * 8 + 2] = to_tf32(fmaxf(p1.x * sc0.z + sh0.z, 0.f));
                dstrow[i * 8 + 3] = to_tf32(fmaxf(p1.y * sc0.w + sh0.w, 0.f));
                dstrow[i * 8 + 4] = to_tf32(fmaxf(p2.x * sc1.x + sh1.x, 0.f));
                dstrow[i * 8 + 5] = to_tf32(fmaxf(p2.y * sc1.y + sh1.y, 0.f));
                dstrow[i * 8 + 6] = to_tf32(fmaxf(p3.x * sc1.z + sh1.z, 0.f));
                dstrow[i * 8 + 7] = to_tf32(fmaxf(p3.y * sc1.w + sh1.w, 0.f));
            }
        }
    }
    __syncthreads();

    int gq = lane >> 2;
    int qr = lane & 3;
    int arow = w * 16;

    float d[8][4];
    #pragma unroll
    for (int nt = 0; nt < 8; nt++)
        #pragma unroll
        for (int j = 0; j < 4; j++) d[nt][j] = 0.f;

    #pragma unroll
    for (int kk = 0; kk < 8; kk++) {
        int kb = kk * 8;
        uint32_t a0 = __float_as_uint(As[(arow + gq) * AP + kb + qr]);
        uint32_t a1 = __float_as_uint(As[(arow + gq + 8) * AP + kb + qr]);
        uint32_t a2 = __float_as_uint(As[(arow + gq) * AP + kb + qr + 4]);
        uint32_t a3 = __float_as_uint(As[(arow + gq + 8) * AP + kb + qr + 4]);
        #pragma unroll
        for (int nt = 0; nt < 8; nt++) {
            int nb = nt * 8;
            uint32_t b0 = __float_as_uint(Bs[(kb + qr) * BP + nb + gq]);
            uint32_t b1 = __float_as_uint(Bs[(kb + qr + 4) * BP + nb + gq]);
            asm volatile(
                "mma.sync.aligned.m16n8k8.row.col.f32.tf32.tf32.f32 "
                "{%0,%1,%2,%3}, {%4,%5,%6,%7}, {%8,%9}, {%0,%1,%2,%3};"
                : "+f"(d[nt][0]), "+f"(d[nt][1]), "+f"(d[nt][2]), "+f"(d[nt][3])
                : "r"(a0), "r"(a1), "r"(a2), "r"(a3), "r"(b0), "r"(b1));
        }
    }

    #pragma unroll
    for (int hf = 0; hf < 2; hf++) {
        int r = row0 + arow + gq + hf * 8;
        if (r < N) {
            float dv = g_dinv[r];
            #pragma unroll
            for (int nt = 0; nt < 8; nt++) {
                __half2 h = __floats2half2_rn(d[nt][hf * 2 + 0] * dv,
                                              d[nt][hf * 2 + 1] * dv);
                *(__half2*)(g_t + (size_t)r * 64 + nt * 8 + 2 * qr) = h;
            }
        }
    }
}

// ---------------- half2 accumulate helper: 4 HADD2 per edge ----------------
__device__ __forceinline__ void h8_add2(uint4 raw, __half2& a0, __half2& a1,
                                        __half2& a2, __half2& a3) {
    a0 = __hadd2(a0, *(__half2*)&raw.x);
    a1 = __hadd2(a1, *(__half2*)&raw.y);
    a2 = __hadd2(a2, *(__half2*)&raw.z);
    a3 = __hadd2(a3, *(__half2*)&raw.w);
}

// ---------------- CSR gather (fp16 rows, HADD2 accumulate) + BN partials -----
// 8 lanes per node; natural node order (coalesced self-reads + acc writes).
__global__ void gather8_k(const float* __restrict__ b, int N) {
    int idx = blockIdx.x * blockDim.x + threadIdx.x;
    int node = idx >> 3;
    int lane = idx & 7;          // owns cols lane*8 .. lane*8+7

    __half2 a0 = __float2half2_rn(0.f), a1 = a0, a2 = a0, a3 = a0;
    float o0 = 0.f, o1 = 0.f, o2 = 0.f, o3 = 0.f,
          o4 = 0.f, o5 = 0.f, o6 = 0.f, o7 = 0.f;

    if (node < N) {
        // self loop
        uint4 raw = *((const uint4*)(g_t + (size_t)node * 64) + lane);
        h8_add2(raw, a0, a1, a2, a3);

        int beg = g_rowstart[node];
        int end = g_rowstart[node + 1];
        int k = beg;
        #pragma unroll 1
        for (; k + 8 <= end; k += 8) {
            uint4 r0 = __ldg((const uint4*)(g_t + (size_t)g_esrc[k + 0] * 64) + lane);
            uint4 r1 = __ldg((const uint4*)(g_t + (size_t)g_esrc[k + 1] * 64) + lane);
            uint4 r2 = __ldg((const uint4*)(g_t + (size_t)g_esrc[k + 2] * 64) + lane);
            uint4 r3 = __ldg((const uint4*)(g_t + (size_t)g_esrc[k + 3] * 64) + lane);
            uint4 r4 = __ldg((const uint4*)(g_t + (size_t)g_esrc[k + 4] * 64) + lane);
            uint4 r5 = __ldg((const uint4*)(g_t + (size_t)g_esrc[k + 5] * 64) + lane);
            uint4 r6 = __ldg((const uint4*)(g_t + (size_t)g_esrc[k + 6] * 64) + lane);
            uint4 r7 = __ldg((const uint4*)(g_t + (size_t)g_esrc[k + 7] * 64) + lane);
            h8_add2(r0, a0, a1, a2, a3); h8_add2(r1, a0, a1, a2, a3);
            h8_add2(r2, a0, a1, a2, a3); h8_add2(r3, a0, a1, a2, a3);
            h8_add2(r4, a0, a1, a2, a3); h8_add2(r5, a0, a1, a2, a3);
            h8_add2(r6, a0, a1, a2, a3); h8_add2(r7, a0, a1, a2, a3);
        }
        if (k + 4 <= end) {
            uint4 r0 = __ldg((const uint4*)(g_t + (size_t)g_esrc[k + 0] * 64) + lane);
            uint4 r1 = __ldg((const uint4*)(g_t + (size_t)g_esrc[k + 1] * 64) + lane);
            uint4 r2 = __ldg((const uint4*)(g_t + (size_t)g_esrc[k + 2] * 64) + lane);
            uint4 r3 = __ldg((const uint4*)(g_t + (size_t)g_esrc[k + 3] * 64) + lane);
            h8_add2(r0, a0, a1, a2, a3); h8_add2(r1, a0, a1, a2, a3);
            h8_add2(r2, a0, a1, a2, a3); h8_add2(r3, a0, a1, a2, a3);
            k += 4;
        }
        if (k + 2 <= end) {
            uint4 r0 = __ldg((const uint4*)(g_t + (size_t)g_esrc[k + 0] * 64) + lane);
            uint4 r1 = __ldg((const uint4*)(g_t + (size_t)g_esrc[k + 1] * 64) + lane);
            h8_add2(r0, a0, a1, a2, a3); h8_add2(r1, a0, a1, a2, a3);
            k += 2;
        }
        if (k < end) {
            uint4 r = __ldg((const uint4*)(g_t + (size_t)g_esrc[k] * 64) + lane);
            h8_add2(r, a0, a1, a2, a3);
        }

        float2 f0 = __half22float2(a0);
        float2 f1 = __half22float2(a1);
        float2 f2 = __half22float2(a2);
        float2 f3 = __half22float2(a3);

        float dv = g_dinv[node];
        float4 bb0 = ((const float4*)b)[lane * 2 + 0];
        float4 bb1 = ((const float4*)b)[lane * 2 + 1];
        o0 = f0.x * dv + bb0.x; o1 = f0.y * dv + bb0.y;
        o2 = f1.x * dv + bb0.z; o3 = f1.y * dv + bb0.w;
        o4 = f2.x * dv + bb1.x; o5 = f2.y * dv + bb1.y;
        o6 = f3.x * dv + bb1.z; o7 = f3.y * dv + bb1.w;

        // store aggregated row as fp16 (BN stats below use the fp32 values)
        __half2 p01 = __floats2half2_rn(o0, o1);
        __half2 p23 = __floats2half2_rn(o2, o3);
        __half2 p45 = __floats2half2_rn(o4, o5);
        __half2 p67 = __floats2half2_rn(o6, o7);
        uint4 ov;
        ov.x = *(unsigned*)&p01; ov.y = *(unsigned*)&p23;
        ov.z = *(unsigned*)&p45; ov.w = *(unsigned*)&p67;
        *((uint4*)(g_acc + (size_t)node * 64) + lane) = ov;
    }

    // --- fused BN partial stats: 32 nodes x 64 cols per block ---
    __shared__ float ssum[32][64];
    __shared__ float ssq[32][64];
    int slot = threadIdx.x >> 3;
    int c = lane * 8;
    ssum[slot][c + 0] = o0; ssq[slot][c + 0] = o0 * o0;
    ssum[slot][c + 1] = o1; ssq[slot][c + 1] = o1 * o1;
    ssum[slot][c + 2] = o2; ssq[slot][c + 2] = o2 * o2;
    ssum[slot][c + 3] = o3; ssq[slot][c + 3] = o3 * o3;
    ssum[slot][c + 4] = o4; ssq[slot][c + 4] = o4 * o4;
    ssum[slot][c + 5] = o5; ssq[slot][c + 5] = o5 * o5;
    ssum[slot][c + 6] = o6; ssq[slot][c + 6] = o6 * o6;
    ssum[slot][c + 7] = o7; ssq[slot][c + 7] = o7 * o7;
    __syncthreads();

    if (threadIdx.x < 64) {
        float s = 0.f, q = 0.f;
        #pragma unroll
        for (int r = 0; r < 32; r++) { s += ssum[r][threadIdx.x]; q += ssq[r][threadIdx.x]; }
        g_psum[blockIdx.x * DD + threadIdx.x] = s;
        g_psq[blockIdx.x * DD + threadIdx.x] = q;
    }
}

// ---------------- BN finalize: 64 blocks, one column each ----------------
__global__ void bn_final_k(const float* __restrict__ gamma,
                           const float* __restrict__ beta, int N, int nblocks) {
    int c = blockIdx.x;
    int t = threadIdx.x;     // 256
    float s = 0.f, q = 0.f;
    for (int b = t; b < nblocks; b += 256) {
        s += g_psum[b * DD + c];
        q += g_psq[b * DD + c];
    }
    __shared__ float sh_s[256], sh_q[256];
    sh_s[t] = s; sh_q[t] = q;
    __syncthreads();
    #pragma unroll
    for (int o = 128; o > 0; o >>= 1) {
        if (t < o) { sh_s[t] += sh_s[t + o]; sh_q[t] += sh_q[t + o]; }
        __syncthreads();
    }
    if (t == 0) {
        float inv_n = 1.0f / (float)N;
        float m = sh_s[0] * inv_n;
        float v = sh_q[0] * inv_n - m * m;
        float sc = gamma[c] * rsqrtf(v + BN_EPS);
        g_scale[c] = sc;
        g_shift[c] = beta[c] - m * sc;
    }
}

// ---------------- mean pool (fused BN+ReLU of last layer, fp16 acc) ----------
__global__ void pool_k(const int* __restrict__ batch, float* __restrict__ out, int N) {
    int col = threadIdx.x;  // 64 threads
    int start = blockIdx.x * 128;
    if (start >= N) return;
    int end = min(start + 128, N);
    float sc = g_scale[col];
    float sh = g_shift[col];
    int g = batch[start];
    float s = 0.f;
    float cnt = 0.f;
    for (int n = start; n < end; n++) {
        int gn = batch[n];
        if (gn != g) {
            atomicAdd(&out[g * 64 + col], s);
            if (col == 0) atomicAdd(&g_gcnt[g], cnt);
            s = 0.f; cnt = 0.f; g = gn;
        }
        float a = __half2float(g_acc[(size_t)n * 64 + col]);
        s += fmaxf(a * sc + sh, 0.f);
        cnt += 1.f;
    }
    atomicAdd(&out[g * 64 + col], s);
    if (col == 0) atomicAdd(&g_gcnt[g], cnt);
}

__global__ void scale_out_k(float* out) {
    int i = blockIdx.x * blockDim.x + threadIdx.x;
    if (i < GG * DD) {
        float c = g_gcnt[i >> 6];
        out[i] /= fmaxf(c, 1.f);
    }
}

// ---------------- host launch: two-stream overlap of gemm0 with CSR build ----
extern "C" void kernel_launch(void* const* d_in, const int* in_sizes, int n_in,
                              void* d_out, int out_size) {
    const float* x      = (const float*)d_in[0];
    const int*   ei     = (const int*)d_in[1];     // int32 (JAX x64 disabled)
    const int*   batch  = (const int*)d_in[2];     // int32
    const float* Ws     = (const float*)d_in[3];
    const float* bs     = (const float*)d_in[4];
    const float* gammas = (const float*)d_in[5];
    const float* betas  = (const float*)d_in[6];
    float*       out    = (float*)d_out;

    int N = in_sizes[0] / DD;   // 100000
    int E = in_sizes[1] / 2;    // 1600000
    const int* src = ei;
    const int* dst = ei + E;

    int tb = 256;
    int nBlk  = (N + tb - 1) / tb;
    int e4Blk = ((E + 3) / 4 + tb - 1) / tb;
    int gaBlk = (N * 8 + tb - 1) / tb;         // 3125
    int gmBlk = (N + 127) / 128;               // 782
    int nScanBlk = (N + SCAN_BS - 1) / SCAN_BS;

    static cudaStream_t sA = nullptr, sB = nullptr;
    static cudaEvent_t ev0 = nullptr, evA = nullptr, evB = nullptr, evA2 = nullptr;
    if (sA == nullptr) {
        cudaStreamCreateWithFlags(&sA, cudaStreamNonBlocking);
        cudaStreamCreateWithFlags(&sB, cudaStreamNonBlocking);
        cudaEventCreateWithFlags(&ev0, cudaEventDisableTiming);
        cudaEventCreateWithFlags(&evA, cudaEventDisableTiming);
        cudaEventCreateWithFlags(&evB, cudaEventDisableTiming);
        cudaEventCreateWithFlags(&evA2, cudaEventDisableTiming);
    }

    init_k<<<nBlk, tb>>>(out, N);                       // launch 1
    cudaEventRecord(ev0, 0);

    cudaStreamWaitEvent(sA, ev0, 0);
    deg_k<<<e4Blk, tb, 0, sA>>>(dst, E);                // launch 2
    scan1_k<<<nScanBlk, SCAN_BS, 0, sA>>>(N);           // launch 3
    cudaEventRecord(evA, sA);

    cudaStreamWaitEvent(sB, evA, 0);
    gemm_mma_k<<<gmBlk, 256, 0, sB>>>(x, Ws, 0, N);     // launch 4 (profiled)
    cudaEventRecord(evB, sB);

    scan3_k<<<nBlk, tb, 0, sA>>>(N, E, nScanBlk);       // launch 5
    perm_k<<<e4Blk, tb, 0, sA>>>(src, dst, E);          // launch 6
    cudaEventRecord(evA2, sA);

    cudaStreamWaitEvent(0, evB, 0);
    cudaStreamWaitEvent(0, evA2, 0);

    for (int l = 0; l < 3; l++) {
        if (l > 0) gemm_mma_k<<<gmBlk, 256>>>(x, Ws + l * DD * DD, l, N);
        gather8_k<<<gaBlk, tb>>>(bs + l * DD, N);
        bn_final_k<<<64, 256>>>(gammas + l * DD, betas + l * DD, N, gaBlk);
    }

    pool_k<<<(N + 127) / 128, 64>>>(batch, out, N);
    scale_out_k<<<(GG * DD + tb - 1) / tb, tb>>>(out);
}